// round 8
// baseline (speedup 1.0000x reference)
#include <cuda_runtime.h>
#include <cuda_fp16.h>
#include <cstdint>
#include <math.h>

#define DIM     2048
#define HIDDEN  5324
#define HPAD    5376      // HIDDEN padded to multiple of 64 (zero-filled)
#define BATCH   16384

// ---------------- scratch (device globals; no allocation allowed) ----------
__device__ float  g_h1 [BATCH * DIM];
__device__ float  g_h2 [BATCH * DIM];
__device__ __half g_hn1[BATCH * DIM];
__device__ __half g_vh [BATCH * DIM];
__device__ __half g_hn2[BATCH * DIM];
__device__ __half g_ffh[(size_t)BATCH * HPAD];
__device__ __half g_wvh [DIM * DIM];
__device__ __half g_owh [DIM * DIM];
__device__ __half g_w1h [(size_t)HIDDEN * DIM];
__device__ __half g_w2h [(size_t)HIDDEN * DIM];
__device__ __half g_w3h [(size_t)DIM * HPAD];

// ---------------- PTX helpers ----------------------------------------------
__device__ __forceinline__ uint32_t smem_u32(const void* p) {
    uint32_t a;
    asm("{ .reg .u64 t; cvta.to.shared.u64 t, %1; cvt.u32.u64 %0, t; }"
        : "=r"(a) : "l"(p));
    return a;
}
__device__ __forceinline__ void cp16(uint32_t dst, const void* src, uint32_t sz) {
    asm volatile("cp.async.cg.shared.global [%0], [%1], 16, %2;"
                 :: "r"(dst), "l"(src), "r"(sz));
}
#define CP_COMMIT()  asm volatile("cp.async.commit_group;" ::: "memory")
#define CP_WAIT2()   asm volatile("cp.async.wait_group 2;" ::: "memory")

__device__ __forceinline__ void ldm4(uint32_t* r, uint32_t addr) {
    asm volatile("ldmatrix.sync.aligned.m8n8.x4.shared.b16 {%0,%1,%2,%3}, [%4];"
                 : "=r"(r[0]), "=r"(r[1]), "=r"(r[2]), "=r"(r[3]) : "r"(addr));
}
__device__ __forceinline__ void mma16(float* c, const uint32_t* a, const uint32_t* b) {
    asm volatile(
        "mma.sync.aligned.m16n8k16.row.col.f32.f16.f16.f32 "
        "{%0,%1,%2,%3}, {%4,%5,%6,%7}, {%8,%9}, {%0,%1,%2,%3};"
        : "+f"(c[0]), "+f"(c[1]), "+f"(c[2]), "+f"(c[3])
        : "r"(a[0]), "r"(a[1]), "r"(a[2]), "r"(a[3]), "r"(b[0]), "r"(b[1]));
}

// ---------------- weight conversion ----------------------------------------
__global__ void __launch_bounds__(256) f2h_kernel(const float* __restrict__ s,
                                                  __half* __restrict__ d, int n4)
{
    int i = blockIdx.x * 256 + threadIdx.x;
    if (i < n4) {
        float4 v = ((const float4*)s)[i];
        __half2* o = (__half2*)d + i * 2;
        o[0] = __floats2half2_rn(v.x, v.y);
        o[1] = __floats2half2_rn(v.z, v.w);
    }
}
__global__ void __launch_bounds__(256) f2h_pad_kernel(const float* __restrict__ s,
                                                      __half* __restrict__ d,
                                                      int rows, int cols, int ldd)
{
    int i = blockIdx.x * 256 + threadIdx.x;
    int total = rows * ldd;
    if (i < total) {
        int r = i / ldd, c = i - r * ldd;
        d[i] = (c < cols) ? __float2half(s[(size_t)r * cols + c]) : __half(0.f);
    }
}

// ---------------- fused (optional add) + rmsnorm -> fp16 --------------------
template <bool ADD>
__global__ void __launch_bounds__(256) rmsnorm_kernel(
    const float* __restrict__ a, const float* __restrict__ b,
    const float* __restrict__ g,
    float* __restrict__ h_out, __half* __restrict__ hn_out)
{
    const int row = blockIdx.x;
    const size_t base = (size_t)row * DIM;
    const float4* a4 = (const float4*)(a + base);
    const float4* b4 = ADD ? (const float4*)(b + base) : nullptr;
    const float4* g4 = (const float4*)g;

    float4 v[2];
    float ss = 0.f;
#pragma unroll
    for (int i = 0; i < 2; i++) {
        int idx = threadIdx.x + i * 256;
        float4 x = a4[idx];
        if (ADD) {
            float4 y = b4[idx];
            x.x += y.x; x.y += y.y; x.z += y.z; x.w += y.w;
        }
        v[i] = x;
        ss += x.x * x.x + x.y * x.y + x.z * x.z + x.w * x.w;
    }
    __shared__ float red[8];
#pragma unroll
    for (int o = 16; o; o >>= 1) ss += __shfl_xor_sync(0xffffffffu, ss, o);
    if ((threadIdx.x & 31) == 0) red[threadIdx.x >> 5] = ss;
    __syncthreads();
    float tot = red[0] + red[1] + red[2] + red[3] + red[4] + red[5] + red[6] + red[7];

    const float norm = sqrtf(tot);
    const float inv  = 0.022097086912079613f / fmaxf(norm, 1e-12f);

    float4*  h4   = ADD ? (float4*)(h_out + base) : nullptr;
    __half2* hn2p = (__half2*)(hn_out + base);
#pragma unroll
    for (int i = 0; i < 2; i++) {
        int idx = threadIdx.x + i * 256;
        float4 x = v[i];
        if (ADD) h4[idx] = x;
        float4 gg = g4[idx];
        hn2p[idx * 2 + 0] = __floats2half2_rn(x.x * inv * gg.x, x.y * inv * gg.y);
        hn2p[idx * 2 + 1] = __floats2half2_rn(x.z * inv * gg.z, x.w * inv * gg.w);
    }
}

// ---------------- fp16 HMMA GEMM: C[M,N] = A[M,K] @ B[N,K]^T (+bias)(+res) -
// CTA 256x128, 8 warps (4x2), warp tile 64x64, m16n8k16, 3-stage cp.async.
// smem/stage: A 256x144B + B 128x144B = 55296 B; 3 stages = 165888 B.
template <bool BIAS, bool RES, bool HALF_OUT>
__global__ void __launch_bounds__(256, 1) gemm_h(
    const __half* __restrict__ A, const __half* __restrict__ B,
    const float* __restrict__ bias, const float* __restrict__ res,
    void* __restrict__ Cv, int N, int K)
{
    extern __shared__ __half sh[];
    const int tid = threadIdx.x, wid = tid >> 5, lane = tid & 31;
    const int q = lane >> 2, t = lane & 3;
    const int m0 = blockIdx.y * 256, n0 = blockIdx.x * 128;
    const int wm = (wid >> 1) * 64, wn = (wid & 1) * 64;
    const int KT = K >> 6;
    const uint32_t sbase = smem_u32(sh);

    auto load = [&](int kc_, int s) {
        const int k0 = kc_ << 6;
        const uint32_t as = sbase + s * 55296u;
        const uint32_t bs = as + 36864u;
#pragma unroll
        for (int i = 0; i < 8; i++) {          // A: 256 rows x 64 halves
            int idx = tid + i * 256;
            int r = idx >> 3, c = idx & 7;
            cp16(as + (uint32_t)(r * 144 + c * 16),
                 A + (size_t)(m0 + r) * K + k0 + c * 8, 16u);
        }
#pragma unroll
        for (int i = 0; i < 4; i++) {          // B: 128 rows x 64 halves
            int idx = tid + i * 256;
            int r = idx >> 3, c = idx & 7;
            cp16(bs + (uint32_t)(r * 144 + c * 16),
                 B + (size_t)(n0 + r) * K + k0 + c * 8, 16u);
        }
        CP_COMMIT();
    };

    float acc[4][8][4] = {};
    load(0, 0);
    load(1, 1);
    load(2, 2);

    const uint32_t a_lane_off = (uint32_t)((lane & 15) * 144 + ((lane >> 4) << 4));
    const uint32_t b_lane_off = (uint32_t)(((lane & 7) + ((lane >> 4) << 3)) * 144
                                           + (((lane >> 3) & 1) << 4));

    int s = 0;
    for (int kc = 0; kc < KT; kc++) {
        CP_WAIT2();
        __syncthreads();
        const uint32_t as = sbase + s * 55296u;
        const uint32_t ab = as + (uint32_t)(wm * 144) + a_lane_off;
        const uint32_t bb = as + 36864u + (uint32_t)(wn * 144) + b_lane_off;
#pragma unroll
        for (int ks = 0; ks < 4; ks++) {
            uint32_t af[4][4], bf[8][2];
#pragma unroll
            for (int mt = 0; mt < 4; mt++)
                ldm4(af[mt], ab + (uint32_t)(mt * 16 * 144 + ks * 32));
#pragma unroll
            for (int p = 0; p < 4; p++) {
                uint32_t r4[4];
                ldm4(r4, bb + (uint32_t)(p * 16 * 144 + ks * 32));
                bf[2 * p][0] = r4[0]; bf[2 * p][1] = r4[1];
                bf[2 * p + 1][0] = r4[2]; bf[2 * p + 1][1] = r4[3];
            }
#pragma unroll
            for (int mt = 0; mt < 4; mt++)
#pragma unroll
                for (int nt = 0; nt < 8; nt++)
                    mma16(acc[mt][nt], af[mt], bf[nt]);
        }
        __syncthreads();
        if (kc + 3 < KT) load(kc + 3, s);
        else             CP_COMMIT();
        s = (s == 2) ? 0 : s + 1;
    }

    // epilogue: c0=(g,2t) c1=(g,2t+1) c2=(g+8,2t) c3=(g+8,2t+1)
#pragma unroll
    for (int mt = 0; mt < 4; mt++) {
#pragma unroll
        for (int half = 0; half < 2; half++) {
            const int r = m0 + wm + mt * 16 + q + half * 8;
#pragma unroll
            for (int nt = 0; nt < 8; nt++) {
                int n = n0 + wn + nt * 8 + 2 * t;
                float vx = acc[mt][nt][half * 2 + 0];
                float vy = acc[mt][nt][half * 2 + 1];
                if (BIAS) { float2 b = *(const float2*)&bias[n]; vx += b.x; vy += b.y; }
                if (RES)  { const float2 rr = *(const float2*)&res[(size_t)r * N + n]; vx += rr.x; vy += rr.y; }
                if (HALF_OUT)
                    *(__half2*)((__half*)Cv + (size_t)r * N + n) = __floats2half2_rn(vx, vy);
                else
                    *(float2*)((float*)Cv + (size_t)r * N + n) = make_float2(vx, vy);
            }
        }
    }
}

// ---------------- fp16 dual GEMM: C = silu(A@B1^T) * (A@B2^T), fp16 out ----
// CTA 128x128, 8 warps (2x4), warp tile 64x32 per matrix, 3-stage cp.async.
// smem/stage: A 128x144B + B1 128x144B + B2 128x144B = 55296 B; 3 stages.
__global__ void __launch_bounds__(256, 1) gemm_dual_h(
    const __half* __restrict__ A, const __half* __restrict__ B1,
    const __half* __restrict__ B2, __half* __restrict__ C,
    int NPAD, int NREAL, int K)
{
    extern __shared__ __half sh[];
    const int tid = threadIdx.x, wid = tid >> 5, lane = tid & 31;
    const int q = lane >> 2, t = lane & 3;
    const int m0 = blockIdx.y * 128, n0 = blockIdx.x * 128;
    const int wm = (wid >> 2) * 64, wn = (wid & 3) * 32;
    const int KT = K >> 6;
    const uint32_t sbase = smem_u32(sh);

    auto load = [&](int kc_, int s) {
        const int k0 = kc_ << 6;
        const uint32_t as  = sbase + s * 55296u;
        const uint32_t b1s = as + 18432u;
        const uint32_t b2s = as + 36864u;
#pragma unroll
        for (int i = 0; i < 4; i++) {          // A: 128 rows
            int idx = tid + i * 256;
            int r = idx >> 3, c = idx & 7;
            cp16(as + (uint32_t)(r * 144 + c * 16),
                 A + (size_t)(m0 + r) * K + k0 + c * 8, 16u);
        }
#pragma unroll
        for (int i = 0; i < 4; i++) {          // B1 + B2: 128 rows each
            int idx = tid + i * 256;
            int r = idx >> 3, c = idx & 7;
            uint32_t ok = (n0 + r < NREAL) ? 16u : 0u;
            size_t off = (size_t)(ok ? (n0 + r) : 0) * K + k0 + c * 8;
            uint32_t sw = (uint32_t)(r * 144 + c * 16);
            cp16(b1s + sw, B1 + off, ok);
            cp16(b2s + sw, B2 + off, ok);
        }
        CP_COMMIT();
    };

    float acc1[4][4][4] = {};
    float acc2[4][4][4] = {};
    load(0, 0);
    load(1, 1);
    load(2, 2);

    const uint32_t a_lane_off = (uint32_t)((lane & 15) * 144 + ((lane >> 4) << 4));
    const uint32_t b_lane_off = (uint32_t)(((lane & 7) + ((lane >> 4) << 3)) * 144
                                           + (((lane >> 3) & 1) << 4));

    int s = 0;
    for (int kc = 0; kc < KT; kc++) {
        CP_WAIT2();
        __syncthreads();
        const uint32_t as  = sbase + s * 55296u;
        const uint32_t ab  = as + (uint32_t)(wm * 144) + a_lane_off;
        const uint32_t b1b = as + 18432u + (uint32_t)(wn * 144) + b_lane_off;
        const uint32_t b2b = as + 36864u + (uint32_t)(wn * 144) + b_lane_off;
#pragma unroll
        for (int ks = 0; ks < 4; ks++) {
            uint32_t af[4][4], b1f[4][2], b2f[4][2];
#pragma unroll
            for (int mt = 0; mt < 4; mt++)
                ldm4(af[mt], ab + (uint32_t)(mt * 16 * 144 + ks * 32));
#pragma unroll
            for (int p = 0; p < 2; p++) {
                uint32_t r4[4];
                ldm4(r4, b1b + (uint32_t)(p * 16 * 144 + ks * 32));
                b1f[2 * p][0] = r4[0]; b1f[2 * p][1] = r4[1];
                b1f[2 * p + 1][0] = r4[2]; b1f[2 * p + 1][1] = r4[3];
                ldm4(r4, b2b + (uint32_t)(p * 16 * 144 + ks * 32));
                b2f[2 * p][0] = r4[0]; b2f[2 * p][1] = r4[1];
                b2f[2 * p + 1][0] = r4[2]; b2f[2 * p + 1][1] = r4[3];
            }
#pragma unroll
            for (int mt = 0; mt < 4; mt++)
#pragma unroll
                for (int nt = 0; nt < 4; nt++) {
                    mma16(acc1[mt][nt], af[mt], b1f[nt]);
                    mma16(acc2[mt][nt], af[mt], b2f[nt]);
                }
        }
        __syncthreads();
        if (kc + 3 < KT) load(kc + 3, s);
        else             CP_COMMIT();
        s = (s == 2) ? 0 : s + 1;
    }

    // epilogue: silu(acc1) * acc2 -> fp16 (pads come out zero)
#pragma unroll
    for (int mt = 0; mt < 4; mt++) {
#pragma unroll
        for (int half = 0; half < 2; half++) {
            const int r = m0 + wm + mt * 16 + q + half * 8;
            __half* Crow = C + (size_t)r * NPAD;
#pragma unroll
            for (int nt = 0; nt < 4; nt++) {
                int n = n0 + wn + nt * 8 + 2 * t;
                float u0 = acc1[mt][nt][half * 2 + 0];
                float u1 = acc1[mt][nt][half * 2 + 1];
                float o0 = u0 / (1.f + expf(-u0)) * acc2[mt][nt][half * 2 + 0];
                float o1 = u1 / (1.f + expf(-u1)) * acc2[mt][nt][half * 2 + 1];
                *(__half2*)&Crow[n] = __floats2half2_rn(o0, o1);
            }
        }
    }
}

// ---------------- launch ---------------------------------------------------
extern "C" void kernel_launch(void* const* d_in, const int* in_sizes, int n_in,
                              void* d_out, int out_size)
{
    const float* x          = (const float*)d_in[0];
    const float* state      = (const float*)d_in[1];
    const float* g1         = (const float*)d_in[2];
    const float* g2         = (const float*)d_in[3];
    const float* in_proj_w  = (const float*)d_in[4];
    const float* in_proj_b  = (const float*)d_in[5];
    const float* out_proj_w = (const float*)d_in[6];
    const float* out_proj_b = (const float*)d_in[7];
    const float* w1         = (const float*)d_in[8];
    const float* w2         = (const float*)d_in[9];
    const float* w3         = (const float*)d_in[10];
    float* out = (float*)d_out;

    const float* wv = in_proj_w + (size_t)2 * DIM * DIM;
    const float* bv = in_proj_b + 2 * DIM;

    float *h1, *h2;  __half *hn1, *vh, *hn2, *ffh, *wvh, *owh, *w1h, *w2h, *w3h;
    cudaGetSymbolAddress((void**)&h1,  g_h1);
    cudaGetSymbolAddress((void**)&h2,  g_h2);
    cudaGetSymbolAddress((void**)&hn1, g_hn1);
    cudaGetSymbolAddress((void**)&vh,  g_vh);
    cudaGetSymbolAddress((void**)&hn2, g_hn2);
    cudaGetSymbolAddress((void**)&ffh, g_ffh);
    cudaGetSymbolAddress((void**)&wvh, g_wvh);
    cudaGetSymbolAddress((void**)&owh, g_owh);
    cudaGetSymbolAddress((void**)&w1h, g_w1h);
    cudaGetSymbolAddress((void**)&w2h, g_w2h);
    cudaGetSymbolAddress((void**)&w3h, g_w3h);

    const int SMEM = 165888;   // 3 stages x 55296 B
    cudaFuncSetAttribute(gemm_h<true,  false, true >, cudaFuncAttributeMaxDynamicSharedMemorySize, SMEM);
    cudaFuncSetAttribute(gemm_h<true,  true,  false>, cudaFuncAttributeMaxDynamicSharedMemorySize, SMEM);
    cudaFuncSetAttribute(gemm_h<false, true,  false>, cudaFuncAttributeMaxDynamicSharedMemorySize, SMEM);
    cudaFuncSetAttribute(gemm_dual_h,                 cudaFuncAttributeMaxDynamicSharedMemorySize, SMEM);

    // 0. weight conversions
    {
        int n4 = DIM * DIM / 4;
        f2h_kernel<<<(n4 + 255) / 256, 256>>>(wv, wvh, n4);
        f2h_kernel<<<(n4 + 255) / 256, 256>>>(out_proj_w, owh, n4);
        n4 = HIDDEN * DIM / 4;
        f2h_kernel<<<(n4 + 255) / 256, 256>>>(w1, w1h, n4);
        f2h_kernel<<<(n4 + 255) / 256, 256>>>(w2, w2h, n4);
        int tot = DIM * HPAD;
        f2h_pad_kernel<<<(tot + 255) / 256, 256>>>(w3, w3h, DIM, HIDDEN, HPAD);
    }

    // 1. h1 = x + state ; hn1 = rmsnorm(h1, g1) -> fp16
    rmsnorm_kernel<true><<<BATCH, 256>>>(x, state, g1, h1, hn1);

    // 2. v = hn1 @ wv^T + bv -> fp16
    gemm_h<true, false, true><<<dim3(DIM / 128, BATCH / 256), 256, SMEM>>>(
        hn1, wvh, bv, nullptr, vh, DIM, DIM);

    // 3. h2 = h1 + v @ out_proj_w^T + out_proj_b -> fp32
    gemm_h<true, true, false><<<dim3(DIM / 128, BATCH / 256), 256, SMEM>>>(
        vh, owh, out_proj_b, h1, h2, DIM, DIM);

    // 4. hn2 = rmsnorm(h2, g2) -> fp16
    rmsnorm_kernel<false><<<BATCH, 256>>>(h2, nullptr, g2, nullptr, hn2);

    // 5. ffh = silu(hn2 @ w1^T) * (hn2 @ w2^T) -> fp16 (padded to HPAD)
    gemm_dual_h<<<dim3(HPAD / 128, BATCH / 128), 256, SMEM>>>(
        hn2, w1h, w2h, ffh, HPAD, HIDDEN, DIM);

    // 6. out = h2 + ffh @ w3^T -> fp32 (K = HPAD, zero-padded)
    gemm_h<false, true, false><<<dim3(DIM / 128, BATCH / 256), 256, SMEM>>>(
        ffh, w3h, nullptr, h2, out, DIM, HPAD);
}

// round 9
// speedup vs baseline: 1.1253x; 1.1253x over previous
#include <cuda_runtime.h>
#include <cuda_fp16.h>
#include <cstdint>
#include <math.h>

#define DIM     2048
#define HIDDEN  5324
#define HPAD    5376
#define BATCH   16384

// ---------------- scratch ---------------------------------------------------
__device__ float  g_h1 [BATCH * DIM];
__device__ float  g_h2 [BATCH * DIM];
__device__ __half g_hn1[BATCH * DIM];
__device__ __half g_vh [BATCH * DIM];
__device__ __half g_hn2[BATCH * DIM];
__device__ __half g_ffh[(size_t)BATCH * HPAD];
__device__ __half g_wvh [DIM * DIM];
__device__ __half g_owh [DIM * DIM];
__device__ __half g_w1h [(size_t)HIDDEN * DIM];
__device__ __half g_w2h [(size_t)HIDDEN * DIM];
__device__ __half g_w3h [(size_t)DIM * HPAD];

// ---------------- PTX helpers ----------------------------------------------
__device__ __forceinline__ uint32_t smem_u32(const void* p) {
    uint32_t a;
    asm("{ .reg .u64 t; cvta.to.shared.u64 t, %1; cvt.u32.u64 %0, t; }"
        : "=r"(a) : "l"(p));
    return a;
}
__device__ __forceinline__ void cp16(uint32_t dst, const void* src, uint32_t sz) {
    asm volatile("cp.async.cg.shared.global [%0], [%1], 16, %2;"
                 :: "r"(dst), "l"(src), "r"(sz));
}
#define CP_COMMIT()  asm volatile("cp.async.commit_group;" ::: "memory")
#define CP_WAIT1()   asm volatile("cp.async.wait_group 1;" ::: "memory")

__device__ __forceinline__ void ldm4(uint32_t* r, uint32_t addr) {
    asm volatile("ldmatrix.sync.aligned.m8n8.x4.shared.b16 {%0,%1,%2,%3}, [%4];"
                 : "=r"(r[0]), "=r"(r[1]), "=r"(r[2]), "=r"(r[3]) : "r"(addr));
}
__device__ __forceinline__ void mma16(float* c, const uint32_t* a, const uint32_t* b) {
    asm volatile(
        "mma.sync.aligned.m16n8k16.row.col.f32.f16.f16.f32 "
        "{%0,%1,%2,%3}, {%4,%5,%6,%7}, {%8,%9}, {%0,%1,%2,%3};"
        : "+f"(c[0]), "+f"(c[1]), "+f"(c[2]), "+f"(c[3])
        : "r"(a[0]), "r"(a[1]), "r"(a[2]), "r"(a[3]), "r"(b[0]), "r"(b[1]));
}

// ---------------- weight conversion ----------------------------------------
__global__ void __launch_bounds__(256) f2h_kernel(const float* __restrict__ s,
                                                  __half* __restrict__ d, int n4)
{
    int i = blockIdx.x * 256 + threadIdx.x;
    if (i < n4) {
        float4 v = ((const float4*)s)[i];
        __half2* o = (__half2*)d + i * 2;
        o[0] = __floats2half2_rn(v.x, v.y);
        o[1] = __floats2half2_rn(v.z, v.w);
    }
}
__global__ void __launch_bounds__(256) f2h_pad_kernel(const float* __restrict__ s,
                                                      __half* __restrict__ d,
                                                      int rows, int cols, int ldd)
{
    int i = blockIdx.x * 256 + threadIdx.x;
    int total = rows * ldd;
    if (i < total) {
        int r = i / ldd, c = i - r * ldd;
        d[i] = (c < cols) ? __float2half(s[(size_t)r * cols + c]) : __half(0.f);
    }
}

// ---------------- fused (optional add) + rmsnorm -> fp16 --------------------
template <bool ADD>
__global__ void __launch_bounds__(256) rmsnorm_kernel(
    const float* __restrict__ a, const float* __restrict__ b,
    const float* __restrict__ g,
    float* __restrict__ h_out, __half* __restrict__ hn_out)
{
    const int row = blockIdx.x;
    const size_t base = (size_t)row * DIM;
    const float4* a4 = (const float4*)(a + base);
    const float4* b4 = ADD ? (const float4*)(b + base) : nullptr;
    const float4* g4 = (const float4*)g;

    float4 v[2];
    float ss = 0.f;
#pragma unroll
    for (int i = 0; i < 2; i++) {
        int idx = threadIdx.x + i * 256;
        float4 x = a4[idx];
        if (ADD) {
            float4 y = b4[idx];
            x.x += y.x; x.y += y.y; x.z += y.z; x.w += y.w;
        }
        v[i] = x;
        ss += x.x * x.x + x.y * x.y + x.z * x.z + x.w * x.w;
    }
    __shared__ float red[8];
#pragma unroll
    for (int o = 16; o; o >>= 1) ss += __shfl_xor_sync(0xffffffffu, ss, o);
    if ((threadIdx.x & 31) == 0) red[threadIdx.x >> 5] = ss;
    __syncthreads();
    float tot = red[0] + red[1] + red[2] + red[3] + red[4] + red[5] + red[6] + red[7];

    const float norm = sqrtf(tot);
    const float inv  = 0.022097086912079613f / fmaxf(norm, 1e-12f);

    float4*  h4   = ADD ? (float4*)(h_out + base) : nullptr;
    __half2* hn2p = (__half2*)(hn_out + base);
#pragma unroll
    for (int i = 0; i < 2; i++) {
        int idx = threadIdx.x + i * 256;
        float4 x = v[i];
        if (ADD) h4[idx] = x;
        float4 gg = g4[idx];
        hn2p[idx * 2 + 0] = __floats2half2_rn(x.x * inv * gg.x, x.y * inv * gg.y);
        hn2p[idx * 2 + 1] = __floats2half2_rn(x.z * inv * gg.z, x.w * inv * gg.w);
    }
}

// ---------------- fp16 HMMA GEMM: C[M,N] = A[M,K] @ B[N,K]^T (+bias)(+res) -
// CTA 128x128, 4 warps (2x2), warp tile 64x64, m16n8k16.
// 3-stage cp.async, ONE __syncthreads per chunk, reg-double-buffered frags.
// smem/stage: A 128x144B + B 128x144B = 36864 B; 3 stages = 110592 B.
template <bool BIAS, bool RES, bool HALF_OUT>
__global__ void __launch_bounds__(128, 2) gemm_h(
    const __half* __restrict__ A, const __half* __restrict__ B,
    const float* __restrict__ bias, const float* __restrict__ res,
    void* __restrict__ Cv, int N, int K)
{
    extern __shared__ __half sh[];
    const int tid = threadIdx.x, wid = tid >> 5, lane = tid & 31;
    const int q = lane >> 2, t = lane & 3;
    const int m0 = blockIdx.y * 128, n0 = blockIdx.x * 128;
    const int wm = (wid >> 1) * 64, wn = (wid & 1) * 64;
    const int KT = K >> 6;
    const uint32_t sbase = smem_u32(sh);

    auto load = [&](int kc_, int s) {
        const int k0 = kc_ << 6;
        const uint32_t as = sbase + s * 36864u;
        const uint32_t bs = as + 18432u;
#pragma unroll
        for (int i = 0; i < 8; i++) {
            int idx = tid + i * 128;
            int r = idx >> 3, c = idx & 7;
            cp16(as + (uint32_t)(r * 144 + c * 16),
                 A + (size_t)(m0 + r) * K + k0 + c * 8, 16u);
        }
#pragma unroll
        for (int i = 0; i < 8; i++) {
            int idx = tid + i * 128;
            int r = idx >> 3, c = idx & 7;
            cp16(bs + (uint32_t)(r * 144 + c * 16),
                 B + (size_t)(n0 + r) * K + k0 + c * 8, 16u);
        }
        CP_COMMIT();
    };

    float acc[4][8][4] = {};
    load(0, 0);
    load(1, 1);

    const uint32_t a_lane_off = (uint32_t)((lane & 15) * 144 + ((lane >> 4) << 4));
    const uint32_t b_lane_off = (uint32_t)(((lane & 7) + ((lane >> 4) << 3)) * 144
                                           + (((lane >> 3) & 1) << 4));

    uint32_t af[2][4][4], bf[2][8][2];

    auto fetch_a = [&](uint32_t ab, int ks, int buf) {
#pragma unroll
        for (int mt = 0; mt < 4; mt++)
            ldm4(af[buf][mt], ab + (uint32_t)(mt * 16 * 144 + ks * 32));
    };
    auto fetch_b = [&](uint32_t bb, int ks, int buf) {
#pragma unroll
        for (int p = 0; p < 4; p++) {
            uint32_t r4[4];
            ldm4(r4, bb + (uint32_t)(p * 16 * 144 + ks * 32));
            bf[buf][2 * p][0] = r4[0]; bf[buf][2 * p][1] = r4[1];
            bf[buf][2 * p + 1][0] = r4[2]; bf[buf][2 * p + 1][1] = r4[3];
        }
    };

    int s = 0;
    for (int kc = 0; kc < KT; kc++) {
        CP_WAIT1();
        __syncthreads();                       // stage s ready for ALL warps
        // refill slot consumed at kc-1 (= slot (kc+2)%3) while computing
        if (kc + 2 < KT) load(kc + 2, (s + 2) % 3);
        else             CP_COMMIT();

        const uint32_t as = sbase + s * 36864u;
        const uint32_t ab = as + (uint32_t)(wm * 144) + a_lane_off;
        const uint32_t bb = as + 18432u + (uint32_t)(wn * 144) + b_lane_off;

        fetch_a(ab, 0, 0);
        fetch_b(bb, 0, 0);
#pragma unroll
        for (int ks = 0; ks < 4; ks++) {
            const int cur = ks & 1, nxt = cur ^ 1;
            if (ks < 3) { fetch_a(ab, ks + 1, nxt); fetch_b(bb, ks + 1, nxt); }
#pragma unroll
            for (int mt = 0; mt < 4; mt++)
#pragma unroll
                for (int nt = 0; nt < 8; nt++)
                    mma16(acc[mt][nt], af[cur][mt], bf[cur][nt]);
        }
        s = (s == 2) ? 0 : s + 1;
    }

    // epilogue: c0=(g,2t) c1=(g,2t+1) c2=(g+8,2t) c3=(g+8,2t+1)
#pragma unroll
    for (int mt = 0; mt < 4; mt++) {
#pragma unroll
        for (int half = 0; half < 2; half++) {
            const int r = m0 + wm + mt * 16 + q + half * 8;
#pragma unroll
            for (int nt = 0; nt < 8; nt++) {
                int n = n0 + wn + nt * 8 + 2 * t;
                float vx = acc[mt][nt][half * 2 + 0];
                float vy = acc[mt][nt][half * 2 + 1];
                if (BIAS) { float2 b = *(const float2*)&bias[n]; vx += b.x; vy += b.y; }
                if (RES)  { const float2 rr = *(const float2*)&res[(size_t)r * N + n]; vx += rr.x; vy += rr.y; }
                if (HALF_OUT)
                    *(__half2*)((__half*)Cv + (size_t)r * N + n) = __floats2half2_rn(vx, vy);
                else
                    *(float2*)((float*)Cv + (size_t)r * N + n) = make_float2(vx, vy);
            }
        }
    }
}

// ---------------- fp16 dual GEMM: C = silu(A@B1^T) * (A@B2^T), fp16 out ----
// CTA 128x64, 4 warps (2x2), warp tile 64x32 per matrix. Same pipeline.
// smem/stage: A 128x144B + B1 64x144B + B2 64x144B = 36864 B; 3 stages.
__global__ void __launch_bounds__(128, 2) gemm_dual_h(
    const __half* __restrict__ A, const __half* __restrict__ B1,
    const __half* __restrict__ B2, __half* __restrict__ C,
    int NPAD, int NREAL, int K)
{
    extern __shared__ __half sh[];
    const int tid = threadIdx.x, wid = tid >> 5, lane = tid & 31;
    const int q = lane >> 2, t = lane & 3;
    const int m0 = blockIdx.y * 128, n0 = blockIdx.x * 64;
    const int wm = (wid >> 1) * 64, wn = (wid & 1) * 32;
    const int KT = K >> 6;
    const uint32_t sbase = smem_u32(sh);

    auto load = [&](int kc_, int s) {
        const int k0 = kc_ << 6;
        const uint32_t as  = sbase + s * 36864u;
        const uint32_t b1s = as + 18432u;
        const uint32_t b2s = as + 27648u;
#pragma unroll
        for (int i = 0; i < 8; i++) {
            int idx = tid + i * 128;
            int r = idx >> 3, c = idx & 7;
            cp16(as + (uint32_t)(r * 144 + c * 16),
                 A + (size_t)(m0 + r) * K + k0 + c * 8, 16u);
        }
#pragma unroll
        for (int i = 0; i < 4; i++) {
            int idx = tid + i * 128;
            int r = idx >> 3, c = idx & 7;
            uint32_t ok = (n0 + r < NREAL) ? 16u : 0u;
            size_t off = (size_t)(ok ? (n0 + r) : 0) * K + k0 + c * 8;
            uint32_t sw = (uint32_t)(r * 144 + c * 16);
            cp16(b1s + sw, B1 + off, ok);
            cp16(b2s + sw, B2 + off, ok);
        }
        CP_COMMIT();
    };

    float acc1[4][4][4] = {};
    float acc2[4][4][4] = {};
    load(0, 0);
    load(1, 1);

    const uint32_t a_lane_off = (uint32_t)((lane & 15) * 144 + ((lane >> 4) << 4));
    const uint32_t b_lane_off = (uint32_t)(((lane & 7) + ((lane >> 4) << 3)) * 144
                                           + (((lane >> 3) & 1) << 4));

    uint32_t af[2][4][4], b1f[2][4][2], b2f[2][4][2];

    auto fetch_a = [&](uint32_t ab, int ks, int buf) {
#pragma unroll
        for (int mt = 0; mt < 4; mt++)
            ldm4(af[buf][mt], ab + (uint32_t)(mt * 16 * 144 + ks * 32));
    };
    auto fetch_b = [&](uint32_t b1b, uint32_t b2b, int ks, int buf) {
#pragma unroll
        for (int p = 0; p < 2; p++) {
            uint32_t r4[4];
            ldm4(r4, b1b + (uint32_t)(p * 16 * 144 + ks * 32));
            b1f[buf][2 * p][0] = r4[0]; b1f[buf][2 * p][1] = r4[1];
            b1f[buf][2 * p + 1][0] = r4[2]; b1f[buf][2 * p + 1][1] = r4[3];
            ldm4(r4, b2b + (uint32_t)(p * 16 * 144 + ks * 32));
            b2f[buf][2 * p][0] = r4[0]; b2f[buf][2 * p][1] = r4[1];
            b2f[buf][2 * p + 1][0] = r4[2]; b2f[buf][2 * p + 1][1] = r4[3];
        }
    };

    int s = 0;
    for (int kc = 0; kc < KT; kc++) {
        CP_WAIT1();
        __syncthreads();
        if (kc + 2 < KT) load(kc + 2, (s + 2) % 3);
        else             CP_COMMIT();

        const uint32_t as  = sbase + s * 36864u;
        const uint32_t ab  = as + (uint32_t)(wm * 144) + a_lane_off;
        const uint32_t b1b = as + 18432u + (uint32_t)(wn * 144) + b_lane_off;
        const uint32_t b2b = as + 27648u + (uint32_t)(wn * 144) + b_lane_off;

        fetch_a(ab, 0, 0);
        fetch_b(b1b, b2b, 0, 0);
#pragma unroll
        for (int ks = 0; ks < 4; ks++) {
            const int cur = ks & 1, nxt = cur ^ 1;
            if (ks < 3) { fetch_a(ab, ks + 1, nxt); fetch_b(b1b, b2b, ks + 1, nxt); }
#pragma unroll
            for (int mt = 0; mt < 4; mt++)
#pragma unroll
                for (int nt = 0; nt < 4; nt++) {
                    mma16(acc1[mt][nt], af[cur][mt], b1f[cur][nt]);
                    mma16(acc2[mt][nt], af[cur][mt], b2f[cur][nt]);
                }
        }
        s = (s == 2) ? 0 : s + 1;
    }

    // epilogue: silu(acc1) * acc2 -> fp16 (pads come out zero)
#pragma unroll
    for (int mt = 0; mt < 4; mt++) {
#pragma unroll
        for (int half = 0; half < 2; half++) {
            const int r = m0 + wm + mt * 16 + q + half * 8;
            __half* Crow = C + (size_t)r * NPAD;
#pragma unroll
            for (int nt = 0; nt < 4; nt++) {
                int n = n0 + wn + nt * 8 + 2 * t;
                float u0 = acc1[mt][nt][half * 2 + 0];
                float u1 = acc1[mt][nt][half * 2 + 1];
                float o0 = u0 / (1.f + expf(-u0)) * acc2[mt][nt][half * 2 + 0];
                float o1 = u1 / (1.f + expf(-u1)) * acc2[mt][nt][half * 2 + 1];
                *(__half2*)&Crow[n] = __floats2half2_rn(o0, o1);
            }
        }
    }
}

// ---------------- launch ---------------------------------------------------
extern "C" void kernel_launch(void* const* d_in, const int* in_sizes, int n_in,
                              void* d_out, int out_size)
{
    const float* x          = (const float*)d_in[0];
    const float* state      = (const float*)d_in[1];
    const float* g1         = (const float*)d_in[2];
    const float* g2         = (const float*)d_in[3];
    const float* in_proj_w  = (const float*)d_in[4];
    const float* in_proj_b  = (const float*)d_in[5];
    const float* out_proj_w = (const float*)d_in[6];
    const float* out_proj_b = (const float*)d_in[7];
    const float* w1         = (const float*)d_in[8];
    const float* w2         = (const float*)d_in[9];
    const float* w3         = (const float*)d_in[10];
    float* out = (float*)d_out;

    const float* wv = in_proj_w + (size_t)2 * DIM * DIM;
    const float* bv = in_proj_b + 2 * DIM;

    float *h1, *h2;  __half *hn1, *vh, *hn2, *ffh, *wvh, *owh, *w1h, *w2h, *w3h;
    cudaGetSymbolAddress((void**)&h1,  g_h1);
    cudaGetSymbolAddress((void**)&h2,  g_h2);
    cudaGetSymbolAddress((void**)&hn1, g_hn1);
    cudaGetSymbolAddress((void**)&vh,  g_vh);
    cudaGetSymbolAddress((void**)&hn2, g_hn2);
    cudaGetSymbolAddress((void**)&ffh, g_ffh);
    cudaGetSymbolAddress((void**)&wvh, g_wvh);
    cudaGetSymbolAddress((void**)&owh, g_owh);
    cudaGetSymbolAddress((void**)&w1h, g_w1h);
    cudaGetSymbolAddress((void**)&w2h, g_w2h);
    cudaGetSymbolAddress((void**)&w3h, g_w3h);

    const int SMEM = 110592;   // 3 stages x 36864 B
    cudaFuncSetAttribute(gemm_h<true,  false, true >, cudaFuncAttributeMaxDynamicSharedMemorySize, SMEM);
    cudaFuncSetAttribute(gemm_h<true,  true,  false>, cudaFuncAttributeMaxDynamicSharedMemorySize, SMEM);
    cudaFuncSetAttribute(gemm_h<false, true,  false>, cudaFuncAttributeMaxDynamicSharedMemorySize, SMEM);
    cudaFuncSetAttribute(gemm_dual_h,                 cudaFuncAttributeMaxDynamicSharedMemorySize, SMEM);

    // 0. weight conversions
    {
        int n4 = DIM * DIM / 4;
        f2h_kernel<<<(n4 + 255) / 256, 256>>>(wv, wvh, n4);
        f2h_kernel<<<(n4 + 255) / 256, 256>>>(out_proj_w, owh, n4);
        n4 = HIDDEN * DIM / 4;
        f2h_kernel<<<(n4 + 255) / 256, 256>>>(w1, w1h, n4);
        f2h_kernel<<<(n4 + 255) / 256, 256>>>(w2, w2h, n4);
        int tot = DIM * HPAD;
        f2h_pad_kernel<<<(tot + 255) / 256, 256>>>(w3, w3h, DIM, HIDDEN, HPAD);
    }

    // 1. h1 = x + state ; hn1 = rmsnorm(h1, g1) -> fp16
    rmsnorm_kernel<true><<<BATCH, 256>>>(x, state, g1, h1, hn1);

    // 2. v = hn1 @ wv^T + bv -> fp16
    gemm_h<true, false, true><<<dim3(DIM / 128, BATCH / 128), 128, SMEM>>>(
        hn1, wvh, bv, nullptr, vh, DIM, DIM);

    // 3. h2 = h1 + v @ out_proj_w^T + out_proj_b -> fp32
    gemm_h<true, true, false><<<dim3(DIM / 128, BATCH / 128), 128, SMEM>>>(
        vh, owh, out_proj_b, h1, h2, DIM, DIM);

    // 4. hn2 = rmsnorm(h2, g2) -> fp16
    rmsnorm_kernel<false><<<BATCH, 256>>>(h2, nullptr, g2, nullptr, hn2);

    // 5. ffh = silu(hn2 @ w1^T) * (hn2 @ w2^T) -> fp16 (padded to HPAD)
    gemm_dual_h<<<dim3(HPAD / 64, BATCH / 128), 128, SMEM>>>(
        hn2, w1h, w2h, ffh, HPAD, HIDDEN, DIM);

    // 6. out = h2 + ffh @ w3^T -> fp32 (K = HPAD, zero-padded)
    gemm_h<false, true, false><<<dim3(DIM / 128, BATCH / 128), 128, SMEM>>>(
        ffh, w3h, nullptr, h2, out, DIM, HPAD);
}